// round 13
// baseline (speedup 1.0000x reference)
#include <cuda_runtime.h>
#include <cuda_bf16.h>
#include <cstdint>
#include <cstddef>

// Problem constants
#define BB   4
#define CC   256
#define CQK  32
#define NN   4096          // H*W = 64*64
#define OUT_ELEMS (BB*CC*NN)
#define NSPLIT 8           // n-dim split for exp pass

#define LOG2E 1.4426950408889634f

// ---------------- scratch (device globals: allocation-free) ----------------
__device__ __align__(128) float g_q[BB*CQK*NN];
__device__ __align__(128) float g_k[BB*CQK*NN];   // pre-scaled by log2(e)
__device__ __align__(128) __nv_bfloat16 g_vh[BB*CC*NN];      // V in bf16
__device__ __align__(128) __nv_bfloat16 g_ah[BB*NN*NN];      // UNNORMALIZED exp map, bf16
__device__ float g_sm[BB*NN];            // inv column sums
__device__ float g_psm[BB*NSPLIT*NN];    // partial column sums

// ---------------- f32x2 packed helpers ----------------
__device__ __forceinline__ unsigned long long f2u_dup(float x) {
    unsigned long long r;
    asm("mov.b64 %0, {%1, %1};" : "=l"(r) : "f"(x));
    return r;
}
__device__ __forceinline__ float2 u2f(unsigned long long v) {
    float2 r;
    asm("mov.b64 {%0, %1}, %2;" : "=f"(r.x), "=f"(r.y) : "l"(v));
    return r;
}
__device__ __forceinline__ unsigned long long fma2(unsigned long long a,
                                                   unsigned long long b,
                                                   unsigned long long c) {
    unsigned long long d;
    asm("fma.rn.f32x2 %0, %1, %2, %3;" : "=l"(d) : "l"(a), "l"(b), "l"(c));
    return d;
}
__device__ __forceinline__ float ex2(float x) {   // 2^x (K pre-scaled by log2e)
    float r;
    asm("ex2.approx.ftz.f32 %0, %1;" : "=f"(r) : "f"(x));
    return r;
}

// ---------------- smem / cp.async helpers ----------------
__device__ __forceinline__ uint32_t smem_u32(const void* p) {
    uint32_t a;
    asm("{ .reg .u64 t; cvta.to.shared.u64 t, %1; cvt.u32.u64 %0, t; }" : "=r"(a) : "l"(p));
    return a;
}
__device__ __forceinline__ void cp16(uint32_t dst, const void* src) {
    asm volatile("cp.async.cg.shared.global [%0], [%1], 16;" :: "r"(dst), "l"(src) : "memory");
}

// =====================================================================
// Kernel 1: q/k projection, f32x2 over output-channel pairs.
// K output pre-multiplied by log2(e) so exp becomes bare ex2.
// grid (NN/256, B, 2[q|k]), block 128.
// =====================================================================
__global__ __launch_bounds__(128)
void proj_qk_kernel(const float* __restrict__ x,
                    const float* __restrict__ wq, const float* __restrict__ bq,
                    const float* __restrict__ wk, const float* __restrict__ bk)
{
    __shared__ float ws[256*40];   // [c][o], row stride 40
    __shared__ float bs[CQK];

    const int sel = blockIdx.z;
    const float* W  = sel ? wk : wq;
    const float* Bv = sel ? bk : bq;
    float* Out      = sel ? g_k : g_q;
    const float osc = sel ? LOG2E : 1.0f;

    const int t = threadIdx.x;
    for (int idx = t; idx < CQK*CC; idx += 128) {
        int o = idx >> 8;
        int c = idx & 255;
        ws[c*40 + o] = W[idx];
    }
    if (t < CQK) bs[t] = Bv[t];
    __syncthreads();

    const int b = blockIdx.y;
    const int n = blockIdx.x * 256 + t*2;

    unsigned long long acc2[2][16];
#pragma unroll
    for (int i = 0; i < 2; i++)
#pragma unroll
        for (int op = 0; op < 16; op++) acc2[i][op] = 0ull;

    const float* xp = x + (size_t)b*CC*NN + n;
#pragma unroll 2
    for (int c = 0; c < CC; c++) {
        float2 xv = *reinterpret_cast<const float2*>(xp + (size_t)c*NN);
        unsigned long long xd0 = f2u_dup(xv.x);
        unsigned long long xd1 = f2u_dup(xv.y);
        const float* wr = &ws[c*40];
#pragma unroll
        for (int op = 0; op < 16; op++) {
            unsigned long long w2 = *reinterpret_cast<const unsigned long long*>(&wr[op*2]);
            acc2[0][op] = fma2(w2, xd0, acc2[0][op]);
            acc2[1][op] = fma2(w2, xd1, acc2[1][op]);
        }
    }
    float* opt = Out + (size_t)b*CQK*NN + n;
#pragma unroll
    for (int op = 0; op < 16; op++) {
        float2 p0 = u2f(acc2[0][op]);
        float2 p1 = u2f(acc2[1][op]);
        float2 r0; r0.x = (p0.x + bs[2*op])*osc;     r0.y = (p1.x + bs[2*op])*osc;
        float2 r1; r1.x = (p0.y + bs[2*op + 1])*osc; r1.y = (p1.y + bs[2*op + 1])*osc;
        *reinterpret_cast<float2*>(opt + (size_t)(2*op)*NN)     = r0;
        *reinterpret_cast<float2*>(opt + (size_t)(2*op + 1)*NN) = r1;
    }
}

// =====================================================================
// Kernel 2: v projection -> bf16, f32x2 over output-channel pairs.
// grid (NN/256, 8, B), block 128; 32 channels per CTA.
// =====================================================================
__global__ __launch_bounds__(128)
void proj_v_kernel(const float* __restrict__ x,
                   const float* __restrict__ wv, const float* __restrict__ bv)
{
    __shared__ float ws[256*40];
    __shared__ float bs[32];

    const int t  = threadIdx.x;
    const int o0 = blockIdx.y * 32;

    for (int idx = t; idx < 32*CC; idx += 128) {
        int o = idx >> 8;
        int c = idx & 255;
        ws[c*40 + o] = wv[(size_t)(o0 + o)*CC + c];
    }
    if (t < 32) bs[t] = bv[o0 + t];
    __syncthreads();

    const int b = blockIdx.z;
    const int n = blockIdx.x * 256 + t*2;

    unsigned long long acc2[2][16];
#pragma unroll
    for (int i = 0; i < 2; i++)
#pragma unroll
        for (int op = 0; op < 16; op++) acc2[i][op] = 0ull;

    const float* xp = x + (size_t)b*CC*NN + n;
#pragma unroll 2
    for (int c = 0; c < CC; c++) {
        float2 xv = *reinterpret_cast<const float2*>(xp + (size_t)c*NN);
        unsigned long long xd0 = f2u_dup(xv.x);
        unsigned long long xd1 = f2u_dup(xv.y);
        const float* wr = &ws[c*40];
#pragma unroll
        for (int op = 0; op < 16; op++) {
            unsigned long long w2 = *reinterpret_cast<const unsigned long long*>(&wr[op*2]);
            acc2[0][op] = fma2(w2, xd0, acc2[0][op]);
            acc2[1][op] = fma2(w2, xd1, acc2[1][op]);
        }
    }
    __nv_bfloat16* opt = g_vh + (size_t)b*CC*NN + (size_t)o0*NN + n;
#pragma unroll
    for (int op = 0; op < 16; op++) {
        float2 p0 = u2f(acc2[0][op]);
        float2 p1 = u2f(acc2[1][op]);
        __nv_bfloat162 h0, h1;
        h0.x = __float2bfloat16_rn(p0.x + bs[2*op]);
        h0.y = __float2bfloat16_rn(p1.x + bs[2*op]);
        h1.x = __float2bfloat16_rn(p0.y + bs[2*op + 1]);
        h1.y = __float2bfloat16_rn(p1.y + bs[2*op + 1]);
        *reinterpret_cast<__nv_bfloat162*>(opt + (size_t)(2*op)*NN)     = h0;
        *reinterpret_cast<__nv_bfloat162*>(opt + (size_t)(2*op + 1)*NN) = h1;
    }
}

// =====================================================================
// Exp pass: energy (log2 domain) + ex2, writes unnormalized fp32 amap
// + bf16 sidecar, accumulates column sums.
// exp overflow-safe: |energy·log2e| <~ 50 << 127.
// grid (NN/64 m-tiles, NSPLIT, B), block 256.
// =====================================================================
__global__ __launch_bounds__(256)
void attn_exp_kernel(float* __restrict__ amap)
{
    __shared__ float Ks[CQK][64];
    __shared__ float Qs[CQK][64];
    __shared__ float reds[64][17];

    const int b  = blockIdx.z;
    const int z  = blockIdx.y;
    const int m0 = blockIdx.x * 64;
    const int t  = threadIdx.x;
    const int tx = t & 15;
    const int ty = t >> 4;

    const float* qb = g_q + (size_t)b*CQK*NN;
    const float* kb = g_k + (size_t)b*CQK*NN;

    for (int idx = t; idx < CQK*64; idx += 256) {
        int c = idx >> 6, j = idx & 63;
        Ks[c][j] = kb[(size_t)c*NN + m0 + j];
    }

    float runsum[4];
#pragma unroll
    for (int j = 0; j < 4; j++) runsum[j] = 0.f;

    for (int nb = 0; nb < NN/(64*NSPLIT); nb++) {
        const int n0 = z*(NN/NSPLIT) + nb * 64;
        __syncthreads();
        for (int idx = t; idx < CQK*64; idx += 256) {
            int c = idx >> 6, j = idx & 63;
            Qs[c][j] = qb[(size_t)c*NN + n0 + j];
        }
        __syncthreads();

        unsigned long long e[4][2];
#pragma unroll
        for (int j = 0; j < 4; j++) { e[j][0] = 0ull; e[j][1] = 0ull; }

#pragma unroll
        for (int c = 0; c < CQK; c++) {
            unsigned long long q01 = *reinterpret_cast<const unsigned long long*>(&Qs[c][tx*4]);
            unsigned long long q23 = *reinterpret_cast<const unsigned long long*>(&Qs[c][tx*4+2]);
            float4 kv = *reinterpret_cast<const float4*>(&Ks[c][ty*4]);
            unsigned long long k0 = f2u_dup(kv.x), k1 = f2u_dup(kv.y),
                               k2 = f2u_dup(kv.z), k3 = f2u_dup(kv.w);
            e[0][0] = fma2(k0, q01, e[0][0]);  e[0][1] = fma2(k0, q23, e[0][1]);
            e[1][0] = fma2(k1, q01, e[1][0]);  e[1][1] = fma2(k1, q23, e[1][1]);
            e[2][0] = fma2(k2, q01, e[2][0]);  e[2][1] = fma2(k2, q23, e[2][1]);
            e[3][0] = fma2(k3, q01, e[3][0]);  e[3][1] = fma2(k3, q23, e[3][1]);
        }

#pragma unroll
        for (int j = 0; j < 4; j++) {
            float2 a  = u2f(e[j][0]);
            float2 c2 = u2f(e[j][1]);
            float4 o;
            o.x = ex2(a.x);
            o.y = ex2(a.y);
            o.z = ex2(c2.x);
            o.w = ex2(c2.y);
            runsum[j] += (o.x + o.y) + (o.z + o.w);
            const size_t row = (size_t)b*NN + (size_t)(m0 + ty*4 + j);
            *reinterpret_cast<float4*>(&amap[row*NN + n0 + tx*4]) = o;
            __nv_bfloat162 h0, h1;
            h0.x = __float2bfloat16_rn(o.x);  h0.y = __float2bfloat16_rn(o.y);
            h1.x = __float2bfloat16_rn(o.z);  h1.y = __float2bfloat16_rn(o.w);
            uint2 packed;
            packed.x = *reinterpret_cast<uint32_t*>(&h0);
            packed.y = *reinterpret_cast<uint32_t*>(&h1);
            *reinterpret_cast<uint2*>(&g_ah[row*NN + n0 + tx*4]) = packed;
        }
    }

#pragma unroll
    for (int j = 0; j < 4; j++) reds[ty*4 + j][tx] = runsum[j];
    __syncthreads();
    if (t < 64) {
        float s = 0.f;
#pragma unroll
        for (int q = 0; q < 16; q++) s += reds[t][q];
        g_psm[((size_t)b*NSPLIT + z)*NN + m0 + t] = s;
    }
}

// =====================================================================
// Reduce: combine NSPLIT partial sums -> inverse. grid (NN/256, B).
// =====================================================================
__global__ __launch_bounds__(256)
void attn_reduce_kernel()
{
    const int b = blockIdx.y;
    const int m = blockIdx.x * 256 + threadIdx.x;
    float s = 0.f;
#pragma unroll
    for (int z = 0; z < NSPLIT; z++)
        s += g_psm[((size_t)b*NSPLIT + z)*NN + m];
    g_sm[(size_t)b*NN + m] = 1.0f / s;
}

// =====================================================================
// Normalize fp32 at_map rows in place (pure bandwidth; overlapped with
// sa_gemm on a second stream). grid (NN/1024, NN, B), block 256.
// =====================================================================
__global__ __launch_bounds__(256)
void attn_norm_kernel(float* __restrict__ amap)
{
    const int b = blockIdx.z;
    const int m = blockIdx.y;
    const float inv = g_sm[(size_t)b*NN + m];
    float4* row = reinterpret_cast<float4*>(amap + ((size_t)(b*NN + m))*NN);
    const int i = blockIdx.x * 256 + threadIdx.x;
    float4 v = row[i];
    v.x *= inv; v.y *= inv; v.z *= inv; v.w *= inv;
    row[i] = v;
}

// =====================================================================
// Kernel 4: SA GEMM via bf16 m16n8k16 + ldmatrix. Reads UNNORMALIZED
// bf16 exp map; epilogue applies gamma * inv_s[m].
// D[c,m] = sum_n Vh[c,n]*Ah[m,n] (NT, both K-contiguous).
// CTA 128(c)x128(m), BK=32, double-buffered cp.async.
// =====================================================================
#define HST 40
#define HSTAGE (128*HST)
#define HSTAGE_B (HSTAGE*2)            // 10240 bytes
#define SAH_SMEM_BYTES (4*HSTAGE_B)    // 40960 bytes

__device__ __forceinline__ void sah_load(uint32_t sbase, int s,
                                         const __nv_bfloat16* Vbh,
                                         const __nv_bfloat16* Abh,
                                         int n0, int t)
{
    const uint32_t voff = sbase + (uint32_t)(s*HSTAGE_B);
    const uint32_t aoff = sbase + (uint32_t)((2 + s)*HSTAGE_B);
#pragma unroll
    for (int it = 0; it < 2; it++) {
        int u = t + it*256;
        int row = u >> 2, q = u & 3;
        uint32_t so = (uint32_t)(row*80 + q*16);
        cp16(voff + so, Vbh + (size_t)row*NN + n0 + q*8);
        cp16(aoff + so, Abh + (size_t)row*NN + n0 + q*8);
    }
}

__global__ __launch_bounds__(256, 2)
void sa_gemm_bf16_kernel(const float* __restrict__ x,
                         const float* __restrict__ gamma,
                         float* __restrict__ dout)
{
    extern __shared__ __nv_bfloat16 hsm[];
    __shared__ float sInv[128];
    const uint32_t sbase = smem_u32(hsm);

    const int t    = threadIdx.x;
    const int w    = t >> 5;
    const int lane = t & 31;
    const int lr   = lane >> 2;
    const int lc   = lane & 3;
    const int wm   = w >> 2;
    const int wn   = w & 3;

    const int b  = blockIdx.z;
    const int c0 = blockIdx.y * 128;
    const int m0 = blockIdx.x * 128;

    const __nv_bfloat16* Vbh = g_vh + (size_t)b*CC*NN + (size_t)c0*NN;
    const __nv_bfloat16* Abh = g_ah + (size_t)b*NN*NN + (size_t)m0*NN;

    if (t < 128) sInv[t] = g_sm[(size_t)b*NN + m0 + t];

    float acc[4][4][4];
#pragma unroll
    for (int mi = 0; mi < 4; mi++)
#pragma unroll
        for (int ni = 0; ni < 4; ni++)
#pragma unroll
            for (int r = 0; r < 4; r++) acc[mi][ni][r] = 0.f;

    sah_load(sbase, 0, Vbh, Abh, 0, t);
    asm volatile("cp.async.commit_group;" ::: "memory");

    const int NCH = NN/32;   // 128
    for (int i = 0; i < NCH; i++) {
        if (i + 1 < NCH) {
            sah_load(sbase, (i+1)&1, Vbh, Abh, (i+1)*32, t);
            asm volatile("cp.async.commit_group;" ::: "memory");
            asm volatile("cp.async.wait_group 1;" ::: "memory");
        } else {
            asm volatile("cp.async.wait_group 0;" ::: "memory");
        }
        __syncthreads();

        const uint32_t vst = sbase + (uint32_t)((i&1)*HSTAGE_B);
        const uint32_t ast = sbase + (uint32_t)((2 + (i&1))*HSTAGE_B);

#pragma unroll
        for (int ks = 0; ks < 2; ks++) {
            const int k0 = ks*16;
            uint32_t afr[4][4], bfr[4][2];
            const uint32_t colA = (uint32_t)((k0 + ((lane & 16) >> 1)) * 2);
#pragma unroll
            for (int mi = 0; mi < 4; mi++) {
                const uint32_t rowA = (uint32_t)(wm*64 + mi*16 + (lane & 15));
                const uint32_t addr = vst + rowA*80 + colA;
                asm volatile(
                    "ldmatrix.sync.aligned.m8n8.x4.shared.b16 {%0,%1,%2,%3}, [%4];"
                    : "=r"(afr[mi][0]), "=r"(afr[mi][1]),
                      "=r"(afr[mi][2]), "=r"(afr[mi][3])
                    : "r"(addr));
            }
            const uint32_t colB = (uint32_t)((k0 + (lane & 8)) * 2);
#pragma unroll
            for (int nb = 0; nb < 2; nb++) {
                const uint32_t rowB = (uint32_t)(wn*32 + nb*16 + (lane & 7) + ((lane & 16) >> 1));
                const uint32_t addr = ast + rowB*80 + colB;
                uint32_t r0, r1, r2, r3;
                asm volatile(
                    "ldmatrix.sync.aligned.m8n8.x4.shared.b16 {%0,%1,%2,%3}, [%4];"
                    : "=r"(r0), "=r"(r1), "=r"(r2), "=r"(r3)
                    : "r"(addr));
                bfr[nb*2    ][0] = r0;  bfr[nb*2    ][1] = r1;
                bfr[nb*2 + 1][0] = r2;  bfr[nb*2 + 1][1] = r3;
            }
#pragma unroll
            for (int mi = 0; mi < 4; mi++)
#pragma unroll
                for (int ni = 0; ni < 4; ni++) {
                    asm volatile(
                        "mma.sync.aligned.m16n8k16.row.col.f32.bf16.bf16.f32 "
                        "{%0,%1,%2,%3}, {%4,%5,%6,%7}, {%8,%9}, {%0,%1,%2,%3};"
                        : "+f"(acc[mi][ni][0]), "+f"(acc[mi][ni][1]),
                          "+f"(acc[mi][ni][2]), "+f"(acc[mi][ni][3])
                        : "r"(afr[mi][0]), "r"(afr[mi][1]),
                          "r"(afr[mi][2]), "r"(afr[mi][3]),
                          "r"(bfr[ni][0]), "r"(bfr[ni][1]));
                }
        }
        __syncthreads();
    }

    // epilogue: out = x + gamma * inv_s[m] * D
    const float g = __ldg(gamma);
#pragma unroll
    for (int mi = 0; mi < 4; mi++) {
        const int r0 = c0 + wm*64 + mi*16 + lr;
#pragma unroll
        for (int ni = 0; ni < 4; ni++) {
            const int cb = wn*32 + ni*8 + lc*2;
            const float s0 = g * sInv[cb];
            const float s1 = g * sInv[cb + 1];
            size_t o1 = ((size_t)(b*CC + r0))*NN + m0 + cb;
            size_t o2 = ((size_t)(b*CC + r0 + 8))*NN + m0 + cb;
            float2 x1 = *reinterpret_cast<const float2*>(x + o1);
            float2 x2 = *reinterpret_cast<const float2*>(x + o2);
            float2 d1, d2;
            d1.x = x1.x + s0*acc[mi][ni][0];
            d1.y = x1.y + s1*acc[mi][ni][1];
            d2.x = x2.x + s0*acc[mi][ni][2];
            d2.y = x2.y + s1*acc[mi][ni][3];
            *reinterpret_cast<float2*>(dout + o1) = d1;
            *reinterpret_cast<float2*>(dout + o2) = d2;
        }
    }
}

// =====================================================================
// launcher: two-stream fork/join (capture-legal event pattern).
//   main: proj_qk -> attn_exp -> reduce -> [wait evV] sa_gemm -> [wait evN]
//   s2:   [wait evA] proj_v (evV)  ...  [wait evR] attn_norm (evN)
// =====================================================================
extern "C" void kernel_launch(void* const* d_in, const int* in_sizes, int n_in,
                              void* d_out, int out_size)
{
    const float* x     = (const float*)d_in[0];
    const float* wq    = (const float*)d_in[1];
    const float* bq    = (const float*)d_in[2];
    const float* wk    = (const float*)d_in[3];
    const float* bk    = (const float*)d_in[4];
    const float* wv    = (const float*)d_in[5];
    const float* bv    = (const float*)d_in[6];
    const float* gamma = (const float*)d_in[7];

    float* out  = (float*)d_out;
    float* amap = out + OUT_ELEMS;

    static cudaStream_t s2 = nullptr;
    static cudaEvent_t evA = nullptr, evV = nullptr, evR = nullptr, evN = nullptr;
    if (!s2) {
        cudaStreamCreateWithFlags(&s2, cudaStreamNonBlocking);
        cudaEventCreateWithFlags(&evA, cudaEventDisableTiming);
        cudaEventCreateWithFlags(&evV, cudaEventDisableTiming);
        cudaEventCreateWithFlags(&evR, cudaEventDisableTiming);
        cudaEventCreateWithFlags(&evN, cudaEventDisableTiming);
    }

    // fork: s2 branches off main stream
    cudaEventRecord(evA, 0);
    cudaStreamWaitEvent(s2, evA, 0);

    // s2: V projection (only sa_gemm consumes it)
    proj_v_kernel<<<dim3(NN/256, 8, BB), 128, 0, s2>>>(x, wv, bv);
    cudaEventRecord(evV, s2);

    // main: q/k projection -> exp pass -> reduce
    proj_qk_kernel<<<dim3(NN/256, BB, 2), 128>>>(x, wq, bq, wk, bk);
    attn_exp_kernel<<<dim3(NN/64, NSPLIT, BB), 256>>>(amap);
    attn_reduce_kernel<<<dim3(NN/256, BB), 256>>>();
    cudaEventRecord(evR, 0);

    // s2: normalize fp32 at_map (independent of sa_gemm)
    cudaStreamWaitEvent(s2, evR, 0);
    attn_norm_kernel<<<dim3(NN/1024, NN, BB), 256, 0, s2>>>(amap);
    cudaEventRecord(evN, s2);

    // main: SA GEMM (needs proj_v result + sums)
    cudaStreamWaitEvent(0, evV, 0);
    sa_gemm_bf16_kernel<<<dim3(NN/128, CC/128, BB), 256, SAH_SMEM_BYTES>>>(x, gamma, out);

    // join
    cudaStreamWaitEvent(0, evN, 0);
}

// round 14
// speedup vs baseline: 1.2127x; 1.2127x over previous
#include <cuda_runtime.h>
#include <cuda_bf16.h>
#include <cstdint>
#include <cstddef>

// Problem constants
#define BB   4
#define CC   256
#define CQK  32
#define NN   4096          // H*W = 64*64
#define OUT_ELEMS (BB*CC*NN)
#define NSPLIT 8           // n-dim split for exp pass

#define LOG2E 1.4426950408889634f

// ---------------- scratch (device globals: allocation-free) ----------------
__device__ __align__(128) float g_q[BB*CQK*NN];
__device__ __align__(128) float g_k[BB*CQK*NN];   // pre-scaled by log2(e)
__device__ __align__(128) __nv_bfloat16 g_vh[BB*CC*NN];      // V in bf16
__device__ __align__(128) __nv_bfloat16 g_ah[BB*NN*NN];      // UNNORMALIZED exp map, bf16
__device__ float g_sm[BB*NN];            // inv column sums
__device__ float g_psm[BB*NSPLIT*NN];    // partial column sums

// ---------------- f32x2 packed helpers ----------------
__device__ __forceinline__ unsigned long long f2u_dup(float x) {
    unsigned long long r;
    asm("mov.b64 %0, {%1, %1};" : "=l"(r) : "f"(x));
    return r;
}
__device__ __forceinline__ float2 u2f(unsigned long long v) {
    float2 r;
    asm("mov.b64 {%0, %1}, %2;" : "=f"(r.x), "=f"(r.y) : "l"(v));
    return r;
}
__device__ __forceinline__ unsigned long long fma2(unsigned long long a,
                                                   unsigned long long b,
                                                   unsigned long long c) {
    unsigned long long d;
    asm("fma.rn.f32x2 %0, %1, %2, %3;" : "=l"(d) : "l"(a), "l"(b), "l"(c));
    return d;
}
__device__ __forceinline__ float ex2(float x) {   // 2^x (K pre-scaled by log2e)
    float r;
    asm("ex2.approx.ftz.f32 %0, %1;" : "=f"(r) : "f"(x));
    return r;
}

// ---------------- smem / cp.async helpers ----------------
__device__ __forceinline__ uint32_t smem_u32(const void* p) {
    uint32_t a;
    asm("{ .reg .u64 t; cvta.to.shared.u64 t, %1; cvt.u32.u64 %0, t; }" : "=r"(a) : "l"(p));
    return a;
}
__device__ __forceinline__ void cp16(uint32_t dst, const void* src) {
    asm volatile("cp.async.cg.shared.global [%0], [%1], 16;" :: "r"(dst), "l"(src) : "memory");
}

// =====================================================================
// Kernel 1: q/k projection, f32x2 over output-channel pairs.
// K output pre-multiplied by log2(e) so exp becomes bare ex2.
// grid (NN/256, B, 2[q|k]), block 128.
// =====================================================================
__global__ __launch_bounds__(128)
void proj_qk_kernel(const float* __restrict__ x,
                    const float* __restrict__ wq, const float* __restrict__ bq,
                    const float* __restrict__ wk, const float* __restrict__ bk)
{
    __shared__ float ws[256*40];   // [c][o], row stride 40
    __shared__ float bs[CQK];

    const int sel = blockIdx.z;
    const float* W  = sel ? wk : wq;
    const float* Bv = sel ? bk : bq;
    float* Out      = sel ? g_k : g_q;
    const float osc = sel ? LOG2E : 1.0f;

    const int t = threadIdx.x;
    for (int idx = t; idx < CQK*CC; idx += 128) {
        int o = idx >> 8;
        int c = idx & 255;
        ws[c*40 + o] = W[idx];
    }
    if (t < CQK) bs[t] = Bv[t];
    __syncthreads();

    const int b = blockIdx.y;
    const int n = blockIdx.x * 256 + t*2;

    unsigned long long acc2[2][16];
#pragma unroll
    for (int i = 0; i < 2; i++)
#pragma unroll
        for (int op = 0; op < 16; op++) acc2[i][op] = 0ull;

    const float* xp = x + (size_t)b*CC*NN + n;
#pragma unroll 2
    for (int c = 0; c < CC; c++) {
        float2 xv = *reinterpret_cast<const float2*>(xp + (size_t)c*NN);
        unsigned long long xd0 = f2u_dup(xv.x);
        unsigned long long xd1 = f2u_dup(xv.y);
        const float* wr = &ws[c*40];
#pragma unroll
        for (int op = 0; op < 16; op++) {
            unsigned long long w2 = *reinterpret_cast<const unsigned long long*>(&wr[op*2]);
            acc2[0][op] = fma2(w2, xd0, acc2[0][op]);
            acc2[1][op] = fma2(w2, xd1, acc2[1][op]);
        }
    }
    float* opt = Out + (size_t)b*CQK*NN + n;
#pragma unroll
    for (int op = 0; op < 16; op++) {
        float2 p0 = u2f(acc2[0][op]);
        float2 p1 = u2f(acc2[1][op]);
        float2 r0; r0.x = (p0.x + bs[2*op])*osc;     r0.y = (p1.x + bs[2*op])*osc;
        float2 r1; r1.x = (p0.y + bs[2*op + 1])*osc; r1.y = (p1.y + bs[2*op + 1])*osc;
        *reinterpret_cast<float2*>(opt + (size_t)(2*op)*NN)     = r0;
        *reinterpret_cast<float2*>(opt + (size_t)(2*op + 1)*NN) = r1;
    }
}

// =====================================================================
// Kernel 2: v projection -> bf16, f32x2 over output-channel pairs.
// grid (NN/256, 8, B), block 128; 32 channels per CTA.
// =====================================================================
__global__ __launch_bounds__(128)
void proj_v_kernel(const float* __restrict__ x,
                   const float* __restrict__ wv, const float* __restrict__ bv)
{
    __shared__ float ws[256*40];
    __shared__ float bs[32];

    const int t  = threadIdx.x;
    const int o0 = blockIdx.y * 32;

    for (int idx = t; idx < 32*CC; idx += 128) {
        int o = idx >> 8;
        int c = idx & 255;
        ws[c*40 + o] = wv[(size_t)(o0 + o)*CC + c];
    }
    if (t < 32) bs[t] = bv[o0 + t];
    __syncthreads();

    const int b = blockIdx.z;
    const int n = blockIdx.x * 256 + t*2;

    unsigned long long acc2[2][16];
#pragma unroll
    for (int i = 0; i < 2; i++)
#pragma unroll
        for (int op = 0; op < 16; op++) acc2[i][op] = 0ull;

    const float* xp = x + (size_t)b*CC*NN + n;
#pragma unroll 2
    for (int c = 0; c < CC; c++) {
        float2 xv = *reinterpret_cast<const float2*>(xp + (size_t)c*NN);
        unsigned long long xd0 = f2u_dup(xv.x);
        unsigned long long xd1 = f2u_dup(xv.y);
        const float* wr = &ws[c*40];
#pragma unroll
        for (int op = 0; op < 16; op++) {
            unsigned long long w2 = *reinterpret_cast<const unsigned long long*>(&wr[op*2]);
            acc2[0][op] = fma2(w2, xd0, acc2[0][op]);
            acc2[1][op] = fma2(w2, xd1, acc2[1][op]);
        }
    }
    __nv_bfloat16* opt = g_vh + (size_t)b*CC*NN + (size_t)o0*NN + n;
#pragma unroll
    for (int op = 0; op < 16; op++) {
        float2 p0 = u2f(acc2[0][op]);
        float2 p1 = u2f(acc2[1][op]);
        __nv_bfloat162 h0, h1;
        h0.x = __float2bfloat16_rn(p0.x + bs[2*op]);
        h0.y = __float2bfloat16_rn(p1.x + bs[2*op]);
        h1.x = __float2bfloat16_rn(p0.y + bs[2*op + 1]);
        h1.y = __float2bfloat16_rn(p1.y + bs[2*op + 1]);
        *reinterpret_cast<__nv_bfloat162*>(opt + (size_t)(2*op)*NN)     = h0;
        *reinterpret_cast<__nv_bfloat162*>(opt + (size_t)(2*op + 1)*NN) = h1;
    }
}

// =====================================================================
// Exp pass: energy (log2 domain) + ex2, writes unnormalized fp32 amap
// + bf16 sidecar, accumulates column sums.
// exp overflow-safe: |energy·log2e| <~ 50 << 127.
// grid (NN/64 m-tiles, NSPLIT, B), block 256.
// =====================================================================
__global__ __launch_bounds__(256)
void attn_exp_kernel(float* __restrict__ amap)
{
    __shared__ float Ks[CQK][64];
    __shared__ float Qs[CQK][64];
    __shared__ float reds[64][17];

    const int b  = blockIdx.z;
    const int z  = blockIdx.y;
    const int m0 = blockIdx.x * 64;
    const int t  = threadIdx.x;
    const int tx = t & 15;
    const int ty = t >> 4;

    const float* qb = g_q + (size_t)b*CQK*NN;
    const float* kb = g_k + (size_t)b*CQK*NN;

    for (int idx = t; idx < CQK*64; idx += 256) {
        int c = idx >> 6, j = idx & 63;
        Ks[c][j] = kb[(size_t)c*NN + m0 + j];
    }

    float runsum[4];
#pragma unroll
    for (int j = 0; j < 4; j++) runsum[j] = 0.f;

    for (int nb = 0; nb < NN/(64*NSPLIT); nb++) {
        const int n0 = z*(NN/NSPLIT) + nb * 64;
        __syncthreads();
        for (int idx = t; idx < CQK*64; idx += 256) {
            int c = idx >> 6, j = idx & 63;
            Qs[c][j] = qb[(size_t)c*NN + n0 + j];
        }
        __syncthreads();

        unsigned long long e[4][2];
#pragma unroll
        for (int j = 0; j < 4; j++) { e[j][0] = 0ull; e[j][1] = 0ull; }

#pragma unroll
        for (int c = 0; c < CQK; c++) {
            unsigned long long q01 = *reinterpret_cast<const unsigned long long*>(&Qs[c][tx*4]);
            unsigned long long q23 = *reinterpret_cast<const unsigned long long*>(&Qs[c][tx*4+2]);
            float4 kv = *reinterpret_cast<const float4*>(&Ks[c][ty*4]);
            unsigned long long k0 = f2u_dup(kv.x), k1 = f2u_dup(kv.y),
                               k2 = f2u_dup(kv.z), k3 = f2u_dup(kv.w);
            e[0][0] = fma2(k0, q01, e[0][0]);  e[0][1] = fma2(k0, q23, e[0][1]);
            e[1][0] = fma2(k1, q01, e[1][0]);  e[1][1] = fma2(k1, q23, e[1][1]);
            e[2][0] = fma2(k2, q01, e[2][0]);  e[2][1] = fma2(k2, q23, e[2][1]);
            e[3][0] = fma2(k3, q01, e[3][0]);  e[3][1] = fma2(k3, q23, e[3][1]);
        }

#pragma unroll
        for (int j = 0; j < 4; j++) {
            float2 a  = u2f(e[j][0]);
            float2 c2 = u2f(e[j][1]);
            float4 o;
            o.x = ex2(a.x);
            o.y = ex2(a.y);
            o.z = ex2(c2.x);
            o.w = ex2(c2.y);
            runsum[j] += (o.x + o.y) + (o.z + o.w);
            const size_t row = (size_t)b*NN + (size_t)(m0 + ty*4 + j);
            *reinterpret_cast<float4*>(&amap[row*NN + n0 + tx*4]) = o;
            __nv_bfloat162 h0, h1;
            h0.x = __float2bfloat16_rn(o.x);  h0.y = __float2bfloat16_rn(o.y);
            h1.x = __float2bfloat16_rn(o.z);  h1.y = __float2bfloat16_rn(o.w);
            uint2 packed;
            packed.x = *reinterpret_cast<uint32_t*>(&h0);
            packed.y = *reinterpret_cast<uint32_t*>(&h1);
            *reinterpret_cast<uint2*>(&g_ah[row*NN + n0 + tx*4]) = packed;
        }
    }

#pragma unroll
    for (int j = 0; j < 4; j++) reds[ty*4 + j][tx] = runsum[j];
    __syncthreads();
    if (t < 64) {
        float s = 0.f;
#pragma unroll
        for (int q = 0; q < 16; q++) s += reds[t][q];
        g_psm[((size_t)b*NSPLIT + z)*NN + m0 + t] = s;
    }
}

// =====================================================================
// Reduce: combine NSPLIT partial sums -> inverse. grid (NN/256, B).
// =====================================================================
__global__ __launch_bounds__(256)
void attn_reduce_kernel()
{
    const int b = blockIdx.y;
    const int m = blockIdx.x * 256 + threadIdx.x;
    float s = 0.f;
#pragma unroll
    for (int z = 0; z < NSPLIT; z++)
        s += g_psm[((size_t)b*NSPLIT + z)*NN + m];
    g_sm[(size_t)b*NN + m] = 1.0f / s;
}

// =====================================================================
// Normalize fp32 at_map rows in place (pure bandwidth).
// grid (NN/1024, NN, B), block 256, one float4 per thread.
// =====================================================================
__global__ __launch_bounds__(256)
void attn_norm_kernel(float* __restrict__ amap)
{
    const int b = blockIdx.z;
    const int m = blockIdx.y;
    const float inv = g_sm[(size_t)b*NN + m];
    float4* row = reinterpret_cast<float4*>(amap + ((size_t)(b*NN + m))*NN);
    const int i = blockIdx.x * 256 + threadIdx.x;
    float4 v = row[i];
    v.x *= inv; v.y *= inv; v.z *= inv; v.w *= inv;
    row[i] = v;
}

// =====================================================================
// Kernel 4: SA GEMM via bf16 m16n8k16 + ldmatrix. Reads UNNORMALIZED
// bf16 exp map; epilogue applies gamma * inv_s[m].
// D[c,m] = sum_n Vh[c,n]*Ah[m,n] (NT, both K-contiguous).
// CTA 128(c)x128(m), BK=32, double-buffered cp.async.
// smem row stride 40 bf16 (80 B) -> conflict-free LDSM + stores.
// =====================================================================
#define HST 40
#define HSTAGE (128*HST)
#define HSTAGE_B (HSTAGE*2)            // 10240 bytes
#define SAH_SMEM_BYTES (4*HSTAGE_B)    // 40960 bytes

__device__ __forceinline__ void sah_load(uint32_t sbase, int s,
                                         const __nv_bfloat16* Vbh,
                                         const __nv_bfloat16* Abh,
                                         int n0, int t)
{
    const uint32_t voff = sbase + (uint32_t)(s*HSTAGE_B);
    const uint32_t aoff = sbase + (uint32_t)((2 + s)*HSTAGE_B);
#pragma unroll
    for (int it = 0; it < 2; it++) {
        int u = t + it*256;
        int row = u >> 2, q = u & 3;
        uint32_t so = (uint32_t)(row*80 + q*16);
        cp16(voff + so, Vbh + (size_t)row*NN + n0 + q*8);
        cp16(aoff + so, Abh + (size_t)row*NN + n0 + q*8);
    }
}

__global__ __launch_bounds__(256, 2)
void sa_gemm_bf16_kernel(const float* __restrict__ x,
                         const float* __restrict__ gamma,
                         float* __restrict__ dout)
{
    extern __shared__ __nv_bfloat16 hsm[];
    __shared__ float sInv[128];
    const uint32_t sbase = smem_u32(hsm);

    const int t    = threadIdx.x;
    const int w    = t >> 5;
    const int lane = t & 31;
    const int lr   = lane >> 2;
    const int lc   = lane & 3;
    const int wm   = w >> 2;
    const int wn   = w & 3;

    const int b  = blockIdx.z;
    const int c0 = blockIdx.y * 128;
    const int m0 = blockIdx.x * 128;

    const __nv_bfloat16* Vbh = g_vh + (size_t)b*CC*NN + (size_t)c0*NN;
    const __nv_bfloat16* Abh = g_ah + (size_t)b*NN*NN + (size_t)m0*NN;

    if (t < 128) sInv[t] = g_sm[(size_t)b*NN + m0 + t];

    float acc[4][4][4];
#pragma unroll
    for (int mi = 0; mi < 4; mi++)
#pragma unroll
        for (int ni = 0; ni < 4; ni++)
#pragma unroll
            for (int r = 0; r < 4; r++) acc[mi][ni][r] = 0.f;

    sah_load(sbase, 0, Vbh, Abh, 0, t);
    asm volatile("cp.async.commit_group;" ::: "memory");

    const int NCH = NN/32;   // 128
    for (int i = 0; i < NCH; i++) {
        if (i + 1 < NCH) {
            sah_load(sbase, (i+1)&1, Vbh, Abh, (i+1)*32, t);
            asm volatile("cp.async.commit_group;" ::: "memory");
            asm volatile("cp.async.wait_group 1;" ::: "memory");
        } else {
            asm volatile("cp.async.wait_group 0;" ::: "memory");
        }
        __syncthreads();

        const uint32_t vst = sbase + (uint32_t)((i&1)*HSTAGE_B);
        const uint32_t ast = sbase + (uint32_t)((2 + (i&1))*HSTAGE_B);

#pragma unroll
        for (int ks = 0; ks < 2; ks++) {
            const int k0 = ks*16;
            uint32_t afr[4][4], bfr[4][2];
            const uint32_t colA = (uint32_t)((k0 + ((lane & 16) >> 1)) * 2);
#pragma unroll
            for (int mi = 0; mi < 4; mi++) {
                const uint32_t rowA = (uint32_t)(wm*64 + mi*16 + (lane & 15));
                const uint32_t addr = vst + rowA*80 + colA;
                asm volatile(
                    "ldmatrix.sync.aligned.m8n8.x4.shared.b16 {%0,%1,%2,%3}, [%4];"
                    : "=r"(afr[mi][0]), "=r"(afr[mi][1]),
                      "=r"(afr[mi][2]), "=r"(afr[mi][3])
                    : "r"(addr));
            }
            const uint32_t colB = (uint32_t)((k0 + (lane & 8)) * 2);
#pragma unroll
            for (int nb = 0; nb < 2; nb++) {
                const uint32_t rowB = (uint32_t)(wn*32 + nb*16 + (lane & 7) + ((lane & 16) >> 1));
                const uint32_t addr = ast + rowB*80 + colB;
                uint32_t r0, r1, r2, r3;
                asm volatile(
                    "ldmatrix.sync.aligned.m8n8.x4.shared.b16 {%0,%1,%2,%3}, [%4];"
                    : "=r"(r0), "=r"(r1), "=r"(r2), "=r"(r3)
                    : "r"(addr));
                bfr[nb*2    ][0] = r0;  bfr[nb*2    ][1] = r1;
                bfr[nb*2 + 1][0] = r2;  bfr[nb*2 + 1][1] = r3;
            }
#pragma unroll
            for (int mi = 0; mi < 4; mi++)
#pragma unroll
                for (int ni = 0; ni < 4; ni++) {
                    asm volatile(
                        "mma.sync.aligned.m16n8k16.row.col.f32.bf16.bf16.f32 "
                        "{%0,%1,%2,%3}, {%4,%5,%6,%7}, {%8,%9}, {%0,%1,%2,%3};"
                        : "+f"(acc[mi][ni][0]), "+f"(acc[mi][ni][1]),
                          "+f"(acc[mi][ni][2]), "+f"(acc[mi][ni][3])
                        : "r"(afr[mi][0]), "r"(afr[mi][1]),
                          "r"(afr[mi][2]), "r"(afr[mi][3]),
                          "r"(bfr[ni][0]), "r"(bfr[ni][1]));
                }
        }
        __syncthreads();
    }

    // epilogue: out = x + gamma * inv_s[m] * D
    const float g = __ldg(gamma);
#pragma unroll
    for (int mi = 0; mi < 4; mi++) {
        const int r0 = c0 + wm*64 + mi*16 + lr;
#pragma unroll
        for (int ni = 0; ni < 4; ni++) {
            const int cb = wn*32 + ni*8 + lc*2;
            const float s0 = g * sInv[cb];
            const float s1 = g * sInv[cb + 1];
            size_t o1 = ((size_t)(b*CC + r0))*NN + m0 + cb;
            size_t o2 = ((size_t)(b*CC + r0 + 8))*NN + m0 + cb;
            float2 x1 = *reinterpret_cast<const float2*>(x + o1);
            float2 x2 = *reinterpret_cast<const float2*>(x + o2);
            float2 d1, d2;
            d1.x = x1.x + s0*acc[mi][ni][0];
            d1.y = x1.y + s1*acc[mi][ni][1];
            d2.x = x2.x + s0*acc[mi][ni][2];
            d2.y = x2.y + s1*acc[mi][ni][3];
            *reinterpret_cast<float2*>(dout + o1) = d1;
            *reinterpret_cast<float2*>(dout + o2) = d2;
        }
    }
}

// =====================================================================
// launcher: single stream (multi-stream measured slower under capture)
// =====================================================================
extern "C" void kernel_launch(void* const* d_in, const int* in_sizes, int n_in,
                              void* d_out, int out_size)
{
    const float* x     = (const float*)d_in[0];
    const float* wq    = (const float*)d_in[1];
    const float* bq    = (const float*)d_in[2];
    const float* wk    = (const float*)d_in[3];
    const float* bk    = (const float*)d_in[4];
    const float* wv    = (const float*)d_in[5];
    const float* bv    = (const float*)d_in[6];
    const float* gamma = (const float*)d_in[7];

    float* out  = (float*)d_out;
    float* amap = out + OUT_ELEMS;

    proj_qk_kernel<<<dim3(NN/256, BB, 2), 128>>>(x, wq, bq, wk, bk);
    proj_v_kernel <<<dim3(NN/256, 8, BB), 128>>>(x, wv, bv);
    attn_exp_kernel<<<dim3(NN/64, NSPLIT, BB), 256>>>(amap);
    attn_reduce_kernel<<<dim3(NN/256, BB), 256>>>();
    attn_norm_kernel<<<dim3(NN/1024, NN, BB), 256>>>(amap);
    sa_gemm_bf16_kernel<<<dim3(NN/128, CC/128, BB), 256, SAH_SMEM_BYTES>>>(x, gamma, out);
}